// round 14
// baseline (speedup 1.0000x reference)
#include <cuda_runtime.h>
#include <cuda_bf16.h>
#include <cstdint>
#include <cstddef>

#define MAXN 50000
#define MAXE 600000
#define HDIM 128

// -------------------- scratch --------------------
__device__ float g_h[(size_t)MAXN * HDIM];
__device__ float g_B[(size_t)MAXN * HDIM];
__device__ float g_C[(size_t)MAXN * HDIM];
__device__ int   g_indeg[MAXN];
__device__ int   g_outdeg[MAXN];
__device__ float g_coef[MAXN];
__device__ int   g_start[MAXN];
__device__ int   g_ptr[MAXN];
__device__ int   g_eid[MAXE];
__device__ __nv_bfloat16 g_Whi[6 * 16384];
__device__ __nv_bfloat16 g_Wlo[6 * 16384];

// -------------------- helpers --------------------
__device__ __forceinline__ uint32_t smem_u32(const void* p) {
    uint32_t a;
    asm("{ .reg .u64 t; cvta.to.shared.u64 t, %1; cvt.u32.u64 %0, t; }" : "=r"(a) : "l"(p));
    return a;
}
__device__ __forceinline__ void ldsm4(uint32_t* r, uint32_t addr) {
    asm volatile("ldmatrix.sync.aligned.m8n8.x4.shared.b16 {%0,%1,%2,%3}, [%4];"
                 : "=r"(r[0]), "=r"(r[1]), "=r"(r[2]), "=r"(r[3]) : "r"(addr));
}
__device__ __forceinline__ void mma_bf16(float* c, const uint32_t* a, uint32_t b0, uint32_t b1) {
    asm volatile("mma.sync.aligned.m16n8k16.row.col.f32.bf16.bf16.f32 "
                 "{%0,%1,%2,%3}, {%4,%5,%6,%7}, {%8,%9}, {%0,%1,%2,%3};"
                 : "+f"(c[0]), "+f"(c[1]), "+f"(c[2]), "+f"(c[3])
                 : "r"(a[0]), "r"(a[1]), "r"(a[2]), "r"(a[3]), "r"(b0), "r"(b1));
}
__device__ __forceinline__ void pdl_wait()   { asm volatile("griddepcontrol.wait;" ::: "memory"); }
__device__ __forceinline__ void pdl_launch() { asm volatile("griddepcontrol.launch_dependents;" ::: "memory"); }

#define RSTRIDE 272
__device__ __forceinline__ uint32_t toff(int r, int k) {
    return (uint32_t)r * RSTRIDE + (uint32_t)k * 2;
}
__device__ __forceinline__ void cvt_store(char* hi, char* lo, uint32_t off, float4 v) {
    __nv_bfloat162 h01 = __floats2bfloat162_rn(v.x, v.y);
    float2 f01 = __bfloat1622float2(h01);
    __nv_bfloat162 l01 = __floats2bfloat162_rn(v.x - f01.x, v.y - f01.y);
    __nv_bfloat162 h23 = __floats2bfloat162_rn(v.z, v.w);
    float2 f23 = __bfloat1622float2(h23);
    __nv_bfloat162 l23 = __floats2bfloat162_rn(v.z - f23.x, v.w - f23.y);
    *(uint32_t*)(hi + off)     = *(uint32_t*)&h01;
    *(uint32_t*)(hi + off + 4) = *(uint32_t*)&h23;
    *(uint32_t*)(lo + off)     = *(uint32_t*)&l01;
    *(uint32_t*)(lo + off + 4) = *(uint32_t*)&l23;
}

// 3-pass merged mainloop over 64x128 A tile (hi/lo) and BNx128 W tile (hi/lo)
template<int NT8>
__device__ __forceinline__ void run_mainloop(
    uint32_t aHi, uint32_t aLo, uint32_t bHi, uint32_t bLo, float acc[2][NT8][4])
{
    #pragma unroll
    for (int mt = 0; mt < 2; mt++)
        #pragma unroll
        for (int nt = 0; nt < NT8; nt++)
            #pragma unroll
            for (int q = 0; q < 4; q++) acc[mt][nt][q] = 0.f;
    #pragma unroll
    for (int ks = 0; ks < 8; ks++) {
        uint32_t afh[8], afl[8];
        ldsm4(afh,     aHi + ks * 32);
        ldsm4(afh + 4, aHi + 16 * RSTRIDE + ks * 32);
        ldsm4(afl,     aLo + ks * 32);
        ldsm4(afl + 4, aLo + 16 * RSTRIDE + ks * 32);
        uint32_t bfh[NT8 * 2], bfl[NT8 * 2];
        #pragma unroll
        for (int nt2 = 0; nt2 < NT8 / 2; nt2++) {
            ldsm4(bfh + nt2 * 4, bHi + nt2 * 16 * RSTRIDE + ks * 32);
            ldsm4(bfl + nt2 * 4, bLo + nt2 * 16 * RSTRIDE + ks * 32);
        }
        #pragma unroll
        for (int mt = 0; mt < 2; mt++)
            #pragma unroll
            for (int nt = 0; nt < NT8; nt++) {
                mma_bf16(acc[mt][nt], afh + mt * 4, bfh[nt * 2], bfh[nt * 2 + 1]);
                mma_bf16(acc[mt][nt], afh + mt * 4, bfl[nt * 2], bfl[nt * 2 + 1]);
                mma_bf16(acc[mt][nt], afl + mt * 4, bfh[nt * 2], bfh[nt * 2 + 1]);
            }
    }
}

// -------------------- weight pre-split --------------------
__global__ void wsplit_kernel(const float* __restrict__ w0, const float* __restrict__ w1,
                              const float* __restrict__ w2, const float* __restrict__ w3,
                              const float* __restrict__ w4, const float* __restrict__ w5)
{
    int i = blockIdx.x * blockDim.x + threadIdx.x;
    int m = i >> 14, off = i & 16383;
    if (m > 5 || (m == 5 && off >= 8192)) return;
    const float* src = (m == 0) ? w0 : (m == 1) ? w1 : (m == 2) ? w2
                     : (m == 3) ? w3 : (m == 4) ? w4 : w5;
    float v = src[off];
    __nv_bfloat16 h = __float2bfloat16_rn(v);
    g_Whi[m * 16384 + off] = h;
    g_Wlo[m * 16384 + off] = __float2bfloat16_rn(v - __bfloat162float(h));
}

// -------------------- single GEMM (BM=64, 2Mx4N warps, 2 CTAs/SM, PDL) -------------------
template<int BN, bool RELU, bool LSM, int PRO>
__global__ __launch_bounds__(256, 2) void gemm_mma(
    const float* __restrict__ A,
    const __nv_bfloat16* __restrict__ Whi, const __nv_bfloat16* __restrict__ Wlo,
    const float* __restrict__ bias, float* __restrict__ C, int M)
{
    constexpr int WN  = BN / 4;
    constexpr int NT8 = WN / 8;
    constexpr int AT  = 64 * RSTRIDE;
    constexpr int WT  = BN * RSTRIDE;
    constexpr int OFF_WHI = 0;
    constexpr int OFF_WLO = WT;
    constexpr int OFF_AHI = 2 * WT;
    constexpr int OFF_ALO = 2 * WT + AT;

    extern __shared__ __align__(16) char smem[];
    const uint32_t sb = smem_u32(smem);
    const int tid = threadIdx.x, wid = tid >> 5, lane = tid & 31;
    const int row0 = blockIdx.x * 64;
    const int warp_m0 = (wid & 1) * 32;
    const int warp_n0 = (wid >> 1) * WN;

    if (PRO == 0) {
        for (int i = tid; i < BN * 16; i += 256) {
            int r = i >> 4, kc = i & 15;
            *(uint4*)(smem + OFF_WHI + toff(r, kc * 8)) = *(const uint4*)(Whi + r * 128 + kc * 8);
            *(uint4*)(smem + OFF_WLO + toff(r, kc * 8)) = *(const uint4*)(Wlo + r * 128 + kc * 8);
        }
        pdl_wait();
        pdl_launch();
        for (int i = tid; i < 64 * 32; i += 256) {
            int r = i >> 5, k = (i & 31) * 4;
            float4 v = make_float4(0.f, 0.f, 0.f, 0.f);
            if (row0 + r < M) v = *(const float4*)(A + (size_t)(row0 + r) * 128 + k);
            cvt_store(smem + OFF_AHI, smem + OFF_ALO, toff(r, k), v);
        }
    } else {
        for (int i = tid; i < 64 * 32; i += 256) {
            int r = i >> 5, k = (i & 31) * 4;
            float4 v = make_float4(0.f, 0.f, 0.f, 0.f);
            if (row0 + r < M) v = *(const float4*)(A + (size_t)(row0 + r) * 128 + k);
            cvt_store(smem + OFF_AHI, smem + OFF_ALO, toff(r, k), v);
        }
        pdl_wait();
        pdl_launch();
        for (int i = tid; i < BN * 16; i += 256) {
            int r = i >> 4, kc = i & 15;
            *(uint4*)(smem + OFF_WHI + toff(r, kc * 8)) = *(const uint4*)(Whi + r * 128 + kc * 8);
            *(uint4*)(smem + OFF_WLO + toff(r, kc * 8)) = *(const uint4*)(Wlo + r * 128 + kc * 8);
        }
    }
    __syncthreads();

    const uint32_t aoff = (uint32_t)(warp_m0 + (lane & 15)) * RSTRIDE + (uint32_t)((lane >> 4) * 8) * 2;
    const int brow = (lane & 7) + (lane >> 4) * 8;
    const int bk   = ((lane >> 3) & 1) * 8;
    const uint32_t boff = (uint32_t)(warp_n0 + brow) * RSTRIDE + (uint32_t)bk * 2;

    float acc[2][NT8][4];
    run_mainloop<NT8>(sb + OFF_AHI + aoff, sb + OFF_ALO + aoff,
                      sb + OFF_WHI + boff, sb + OFF_WLO + boff, acc);

    const int colq = (lane & 3) * 2;
    if (!LSM) {
        #pragma unroll
        for (int mt = 0; mt < 2; mt++) {
            int r0 = row0 + warp_m0 + mt * 16 + (lane >> 2);
            #pragma unroll
            for (int nt = 0; nt < NT8; nt++) {
                int col = warp_n0 + nt * 8 + colq;
                float2 b2 = *(const float2*)(bias + col);
                float2 o0, o1;
                o0.x = acc[mt][nt][0] + b2.x; o0.y = acc[mt][nt][1] + b2.y;
                o1.x = acc[mt][nt][2] + b2.x; o1.y = acc[mt][nt][3] + b2.y;
                if (RELU) {
                    o0.x = fmaxf(o0.x, 0.f); o0.y = fmaxf(o0.y, 0.f);
                    o1.x = fmaxf(o1.x, 0.f); o1.y = fmaxf(o1.y, 0.f);
                }
                if (r0 < M)     *(float2*)(C + (size_t)r0 * BN + col)       = o0;
                if (r0 + 8 < M) *(float2*)(C + (size_t)(r0 + 8) * BN + col) = o1;
            }
        }
    } else {
        __syncthreads();
        float* Cs = (float*)smem;  // [64][68]
        #pragma unroll
        for (int mt = 0; mt < 2; mt++) {
            int rr = warp_m0 + mt * 16 + (lane >> 2);
            #pragma unroll
            for (int nt = 0; nt < NT8; nt++) {
                int col = warp_n0 + nt * 8 + colq;
                float2 b2 = *(const float2*)(bias + col);
                Cs[rr * 68 + col]            = acc[mt][nt][0] + b2.x;
                Cs[rr * 68 + col + 1]        = acc[mt][nt][1] + b2.y;
                Cs[(rr + 8) * 68 + col]      = acc[mt][nt][2] + b2.x;
                Cs[(rr + 8) * 68 + col + 1]  = acc[mt][nt][3] + b2.y;
            }
        }
        __syncthreads();
        #pragma unroll
        for (int it = 0; it < 8; it++) {
            int r = wid + it * 8;
            float2 v = *(float2*)&Cs[r * 68 + lane * 2];
            float m = fmaxf(v.x, v.y);
            #pragma unroll
            for (int o = 16; o; o >>= 1) m = fmaxf(m, __shfl_xor_sync(0xffffffffu, m, o));
            float s = expf(v.x - m) + expf(v.y - m);
            #pragma unroll
            for (int o = 16; o; o >>= 1) s += __shfl_xor_sync(0xffffffffu, s, o);
            float ls = logf(s) + m;
            int gr = row0 + r;
            if (gr < M)
                *(float2*)(C + (size_t)gr * 64 + lane * 2) = make_float2(v.x - ls, v.y - ls);
        }
    }
}

// -------------------- fused GIN MLP: C = relu( relu(A W1^T + b1) W2^T + b2 ) --------------
__global__ __launch_bounds__(256, 2) void gin_mlp(
    const float* __restrict__ A,
    const __nv_bfloat16* __restrict__ W1hi, const __nv_bfloat16* __restrict__ W1lo,
    const float* __restrict__ b1,
    const __nv_bfloat16* __restrict__ W2hi, const __nv_bfloat16* __restrict__ W2lo,
    const float* __restrict__ b2, float* __restrict__ C, int M)
{
    constexpr int NT8 = 4;
    constexpr int AT  = 64 * RSTRIDE;
    constexpr int WT  = 128 * RSTRIDE;
    constexpr int OFF_WHI = 0;
    constexpr int OFF_WLO = WT;
    constexpr int OFF_AHI = 2 * WT;
    constexpr int OFF_ALO = 2 * WT + AT;

    extern __shared__ __align__(16) char smem[];
    const uint32_t sb = smem_u32(smem);
    const int tid = threadIdx.x, wid = tid >> 5, lane = tid & 31;
    const int row0 = blockIdx.x * 64;
    const int warp_m0 = (wid & 1) * 32;
    const int warp_n0 = (wid >> 1) * 32;

    for (int i = tid; i < 128 * 16; i += 256) {
        int r = i >> 4, kc = i & 15;
        *(uint4*)(smem + OFF_WHI + toff(r, kc * 8)) = *(const uint4*)(W1hi + r * 128 + kc * 8);
        *(uint4*)(smem + OFF_WLO + toff(r, kc * 8)) = *(const uint4*)(W1lo + r * 128 + kc * 8);
    }
    pdl_wait();
    pdl_launch();
    for (int i = tid; i < 64 * 32; i += 256) {
        int r = i >> 5, k = (i & 31) * 4;
        float4 v = make_float4(0.f, 0.f, 0.f, 0.f);
        if (row0 + r < M) v = *(const float4*)(A + (size_t)(row0 + r) * 128 + k);
        cvt_store(smem + OFF_AHI, smem + OFF_ALO, toff(r, k), v);
    }
    __syncthreads();

    const uint32_t aoff = (uint32_t)(warp_m0 + (lane & 15)) * RSTRIDE + (uint32_t)((lane >> 4) * 8) * 2;
    const int brow = (lane & 7) + (lane >> 4) * 8;
    const int bk   = ((lane >> 3) & 1) * 8;
    const uint32_t boff = (uint32_t)(warp_n0 + brow) * RSTRIDE + (uint32_t)bk * 2;
    const uint32_t aHi = sb + OFF_AHI + aoff, aLo = sb + OFF_ALO + aoff;
    const uint32_t bHi = sb + OFF_WHI + boff, bLo = sb + OFF_WLO + boff;

    float acc[2][NT8][4];
    run_mainloop<NT8>(aHi, aLo, bHi, bLo, acc);
    __syncthreads();

    const int colq = (lane & 3) * 2;
    #pragma unroll
    for (int mt = 0; mt < 2; mt++) {
        int rr = warp_m0 + mt * 16 + (lane >> 2);
        #pragma unroll
        for (int nt = 0; nt < NT8; nt++) {
            int col = warp_n0 + nt * 8 + colq;
            float2 bb = *(const float2*)(b1 + col);
            float z0 = fmaxf(acc[mt][nt][0] + bb.x, 0.f);
            float z1 = fmaxf(acc[mt][nt][1] + bb.y, 0.f);
            float z2 = fmaxf(acc[mt][nt][2] + bb.x, 0.f);
            float z3 = fmaxf(acc[mt][nt][3] + bb.y, 0.f);
            __nv_bfloat162 h0 = __floats2bfloat162_rn(z0, z1);
            float2 f0 = __bfloat1622float2(h0);
            __nv_bfloat162 l0 = __floats2bfloat162_rn(z0 - f0.x, z1 - f0.y);
            __nv_bfloat162 h1 = __floats2bfloat162_rn(z2, z3);
            float2 f1 = __bfloat1622float2(h1);
            __nv_bfloat162 l1 = __floats2bfloat162_rn(z2 - f1.x, z3 - f1.y);
            *(uint32_t*)(smem + OFF_AHI + toff(rr, col))     = *(uint32_t*)&h0;
            *(uint32_t*)(smem + OFF_ALO + toff(rr, col))     = *(uint32_t*)&l0;
            *(uint32_t*)(smem + OFF_AHI + toff(rr + 8, col)) = *(uint32_t*)&h1;
            *(uint32_t*)(smem + OFF_ALO + toff(rr + 8, col)) = *(uint32_t*)&l1;
        }
    }
    for (int i = tid; i < 128 * 16; i += 256) {
        int r = i >> 4, kc = i & 15;
        *(uint4*)(smem + OFF_WHI + toff(r, kc * 8)) = *(const uint4*)(W2hi + r * 128 + kc * 8);
        *(uint4*)(smem + OFF_WLO + toff(r, kc * 8)) = *(const uint4*)(W2lo + r * 128 + kc * 8);
    }
    __syncthreads();

    run_mainloop<NT8>(aHi, aLo, bHi, bLo, acc);

    #pragma unroll
    for (int mt = 0; mt < 2; mt++) {
        int r0 = row0 + warp_m0 + mt * 16 + (lane >> 2);
        #pragma unroll
        for (int nt = 0; nt < NT8; nt++) {
            int col = warp_n0 + nt * 8 + colq;
            float2 bb = *(const float2*)(b2 + col);
            float2 o0, o1;
            o0.x = fmaxf(acc[mt][nt][0] + bb.x, 0.f);
            o0.y = fmaxf(acc[mt][nt][1] + bb.y, 0.f);
            o1.x = fmaxf(acc[mt][nt][2] + bb.x, 0.f);
            o1.y = fmaxf(acc[mt][nt][3] + bb.y, 0.f);
            if (r0 < M)     *(float2*)(C + (size_t)r0 * 128 + col)       = o0;
            if (r0 + 8 < M) *(float2*)(C + (size_t)(r0 + 8) * 128 + col) = o1;
        }
    }
}

// -------------------- CSR build (4 kernels, PDL-chained) --------------------
__global__ void zero_deg_kernel(int n) {
    pdl_launch();
    int i = blockIdx.x * blockDim.x + threadIdx.x;
    if (i < n) { g_indeg[i] = 0; g_outdeg[i] = 0; }
}
__global__ void hist_kernel(const int* __restrict__ row, const int* __restrict__ col, int E) {
    int e = blockIdx.x * blockDim.x + threadIdx.x;
    int r = 0, c = 0;
    if (e < E) { r = row[e]; c = col[e]; }   // prologue: edge loads (zero-independent)
    pdl_wait();
    pdl_launch();
    if (e < E) {
        atomicAdd(&g_indeg[c], 1);
        atomicAdd(&g_outdeg[r], 1);
    }
}
// single-block fused scan+finalize: exclusive scan of g_indeg -> g_start/g_ptr; coef
__global__ __launch_bounds__(1024) void scan_finalize_kernel(int n) {
    __shared__ int wsum[32];
    pdl_wait();
    pdl_launch();
    const int C = (n + 1023) >> 10;
    int t = threadIdx.x, lane = t & 31, w = t >> 5;
    int base = t * C;
    int sum = 0;
    for (int i = 0; i < C; i++) {
        int idx = base + i;
        if (idx < n) sum += g_indeg[idx];
    }
    int v = sum;
    #pragma unroll
    for (int o = 1; o < 32; o <<= 1) {
        int x = __shfl_up_sync(0xffffffffu, v, o);
        if (lane >= o) v += x;
    }
    if (lane == 31) wsum[w] = v;
    __syncthreads();
    if (w == 0) {
        int s = wsum[lane];
        #pragma unroll
        for (int o = 1; o < 32; o <<= 1) {
            int x = __shfl_up_sync(0xffffffffu, s, o);
            if (lane >= o) s += x;
        }
        wsum[lane] = s;
    }
    __syncthreads();
    int run = v - sum + (w > 0 ? wsum[w - 1] : 0);
    for (int i = 0; i < C; i++) {
        int idx = base + i;
        if (idx < n) {
            g_start[idx] = run;
            g_ptr[idx]   = run;
            run += g_indeg[idx];
            g_coef[idx]  = 1.0f / (float)(g_outdeg[idx] + 1);
        }
    }
}
__global__ void scatter_kernel(const int* __restrict__ row, const int* __restrict__ col, int E) {
    int e = blockIdx.x * blockDim.x + threadIdx.x;
    int r = 0, c = 0;
    if (e < E) { r = row[e]; c = col[e]; }   // prologue: edge loads (scan-independent)
    pdl_wait();
    pdl_launch();
    if (e < E) {
        int p = atomicAdd(&g_ptr[c], 1);
        g_eid[p] = r;
    }
}

// -------------------- gather aggregation (fp32, 4-deep pipelined, PDL) ------------------
template<bool ATT>
__global__ void agg_kernel(const float* __restrict__ src, float* __restrict__ dst, int n) {
    int node = (blockIdx.x * blockDim.x + threadIdx.x) >> 5;
    int lane = threadIdx.x & 31;
    if (node >= n) { pdl_wait(); pdl_launch(); return; }
    int s = g_start[node], e = s + g_indeg[node];
    float cself = ATT ? g_coef[node] : 1.0f;
    int myeid = (s + lane < e) ? __ldg(&g_eid[s + lane]) : 0;
    pdl_wait();
    pdl_launch();
    float4 a0 = *(const float4*)(src + (size_t)node * 128 + lane * 4);
    if (ATT) { a0.x *= cself; a0.y *= cself; a0.z *= cself; a0.w *= cself; }
    float4 a1 = make_float4(0.f, 0.f, 0.f, 0.f);
    float4 a2 = make_float4(0.f, 0.f, 0.f, 0.f);
    float4 a3 = make_float4(0.f, 0.f, 0.f, 0.f);
    for (int j0 = s; j0 < e; j0 += 32) {
        int nb = min(32, e - j0);
        int cur = myeid;
        int jn = j0 + 32;
        if (jn < e) myeid = (jn + lane < e) ? __ldg(&g_eid[jn + lane]) : 0;
        int t = 0;
        for (; t + 3 < nb; t += 4) {
            int r0 = __shfl_sync(0xffffffffu, cur, t);
            int r1 = __shfl_sync(0xffffffffu, cur, t + 1);
            int r2 = __shfl_sync(0xffffffffu, cur, t + 2);
            int r3 = __shfl_sync(0xffffffffu, cur, t + 3);
            float4 v0 = *(const float4*)(src + (size_t)r0 * 128 + lane * 4);
            float4 v1 = *(const float4*)(src + (size_t)r1 * 128 + lane * 4);
            float4 v2 = *(const float4*)(src + (size_t)r2 * 128 + lane * 4);
            float4 v3 = *(const float4*)(src + (size_t)r3 * 128 + lane * 4);
            float c0 = ATT ? g_coef[r0] : 1.0f;
            float c1 = ATT ? g_coef[r1] : 1.0f;
            float c2 = ATT ? g_coef[r2] : 1.0f;
            float c3 = ATT ? g_coef[r3] : 1.0f;
            a0.x = fmaf(c0, v0.x, a0.x); a0.y = fmaf(c0, v0.y, a0.y);
            a0.z = fmaf(c0, v0.z, a0.z); a0.w = fmaf(c0, v0.w, a0.w);
            a1.x = fmaf(c1, v1.x, a1.x); a1.y = fmaf(c1, v1.y, a1.y);
            a1.z = fmaf(c1, v1.z, a1.z); a1.w = fmaf(c1, v1.w, a1.w);
            a2.x = fmaf(c2, v2.x, a2.x); a2.y = fmaf(c2, v2.y, a2.y);
            a2.z = fmaf(c2, v2.z, a2.z); a2.w = fmaf(c2, v2.w, a2.w);
            a3.x = fmaf(c3, v3.x, a3.x); a3.y = fmaf(c3, v3.y, a3.y);
            a3.z = fmaf(c3, v3.z, a3.z); a3.w = fmaf(c3, v3.w, a3.w);
        }
        for (; t < nb; t++) {
            int r0 = __shfl_sync(0xffffffffu, cur, t);
            float4 v0 = *(const float4*)(src + (size_t)r0 * 128 + lane * 4);
            float c0 = ATT ? g_coef[r0] : 1.0f;
            a0.x = fmaf(c0, v0.x, a0.x); a0.y = fmaf(c0, v0.y, a0.y);
            a0.z = fmaf(c0, v0.z, a0.z); a0.w = fmaf(c0, v0.w, a0.w);
        }
    }
    float4 acc;
    acc.x = (a0.x + a1.x) + (a2.x + a3.x);
    acc.y = (a0.y + a1.y) + (a2.y + a3.y);
    acc.z = (a0.z + a1.z) + (a2.z + a3.z);
    acc.w = (a0.w + a1.w) + (a2.w + a3.w);
    if (ATT) {
        acc.x = fmaxf(acc.x, 0.f); acc.y = fmaxf(acc.y, 0.f);
        acc.z = fmaxf(acc.z, 0.f); acc.w = fmaxf(acc.w, 0.f);
    }
    *(float4*)(dst + (size_t)node * 128 + lane * 4) = acc;
}

// -------------------- launch --------------------
extern "C" void kernel_launch(void* const* d_in, const int* in_sizes, int n_in,
                              void* d_out, int out_size)
{
    const float* x     = (const float*)d_in[0];
    const int*   ei    = (const int*)  d_in[1];
    const float* fl_W  = (const float*)d_in[2];
    const float* fl_b  = (const float*)d_in[3];
    // d_in[4] = fl_att : softmax over identical per-segment logits is uniform -> unused
    const float* g1_W1 = (const float*)d_in[5];
    const float* g1_b1 = (const float*)d_in[6];
    const float* g1_W2 = (const float*)d_in[7];
    const float* g1_b2 = (const float*)d_in[8];
    const float* g2_W1 = (const float*)d_in[9];
    const float* g2_b1 = (const float*)d_in[10];
    const float* g2_W2 = (const float*)d_in[11];
    const float* g2_b2 = (const float*)d_in[12];
    const float* out_W = (const float*)d_in[13];
    const float* out_b = (const float*)d_in[14];
    float* out = (float*)d_out;

    const int N = in_sizes[0] / HDIM;
    const int E = in_sizes[1] / 2;
    const int* row = ei;
    const int* col = ei + E;

    float *pH = nullptr, *pB = nullptr, *pC = nullptr;
    __nv_bfloat16 *pWhi = nullptr, *pWlo = nullptr;
    cudaGetSymbolAddress((void**)&pH, g_h);
    cudaGetSymbolAddress((void**)&pB, g_B);
    cudaGetSymbolAddress((void**)&pC, g_C);
    cudaGetSymbolAddress((void**)&pWhi, g_Whi);
    cudaGetSymbolAddress((void**)&pWlo, g_Wlo);

    const int smem128 = 2 * 128 * RSTRIDE + 2 * 64 * RSTRIDE;  // 104448
    const int smem64  = 4 * 64 * RSTRIDE;                      // 69632
    cudaFuncSetAttribute(gemm_mma<128, false, false, 1>, cudaFuncAttributeMaxDynamicSharedMemorySize, smem128);
    cudaFuncSetAttribute(gin_mlp,                        cudaFuncAttributeMaxDynamicSharedMemorySize, smem128);
    cudaFuncSetAttribute(gemm_mma<64,  false, true,  0>, cudaFuncAttributeMaxDynamicSharedMemorySize, smem64);

    static cudaStream_t s_side = [] {
        cudaStream_t s; cudaStreamCreateWithFlags(&s, cudaStreamNonBlocking); return s;
    }();
    static cudaEvent_t s_fork = [] {
        cudaEvent_t e; cudaEventCreateWithFlags(&e, cudaEventDisableTiming); return e;
    }();
    static cudaEvent_t s_join = [] {
        cudaEvent_t e; cudaEventCreateWithFlags(&e, cudaEventDisableTiming); return e;
    }();

    const int T = 256;
    const int gemmGrid  = (N + 63) / 64;
    const int edgeThG   = (E + T - 1) / T;
    const int nodeThG   = (N + T - 1) / T;
    const int nodeWarpG = (N * 32 + T - 1) / T;

    cudaLaunchAttribute pdlAttr[1];
    pdlAttr[0].id = cudaLaunchAttributeProgrammaticStreamSerialization;
    pdlAttr[0].val.programmaticStreamSerializationAllowed = 1;
    auto mkCfg = [&](int grid, int blk, int smem, cudaStream_t st) {
        cudaLaunchConfig_t c = {};
        c.gridDim = dim3(grid); c.blockDim = dim3(blk);
        c.dynamicSmemBytes = (size_t)smem; c.stream = st;
        c.attrs = pdlAttr; c.numAttrs = 1;
        return c;
    };

    // ---- fork: CSR build on side stream (PDL-chained); wsplit+gemm1 on main ----
    cudaEventRecord(s_fork, 0);
    cudaStreamWaitEvent(s_side, s_fork, 0);

    { cudaLaunchConfig_t c = mkCfg(nodeThG, T, 0, s_side);
      cudaLaunchKernelEx(&c, zero_deg_kernel, N); }
    { cudaLaunchConfig_t c = mkCfg(edgeThG, T, 0, s_side);
      cudaLaunchKernelEx(&c, hist_kernel, row, col, E); }
    { cudaLaunchConfig_t c = mkCfg(1, 1024, 0, s_side);
      cudaLaunchKernelEx(&c, scan_finalize_kernel, N); }
    { cudaLaunchConfig_t c = mkCfg(edgeThG, T, 0, s_side);
      cudaLaunchKernelEx(&c, scatter_kernel, row, col, E); }
    cudaEventRecord(s_join, s_side);

    wsplit_kernel<<<(6 * 16384 + T - 1) / T, T>>>(fl_W, g1_W1, g1_W2, g2_W1, g2_W2, out_W);
    {   // gemm1: stage A(x) during wsplit tail (PRO=1)
        cudaLaunchConfig_t c = mkCfg(gemmGrid, T, smem128, 0);
        cudaLaunchKernelEx(&c, gemm_mma<128, false, false, 1>, x, (const __nv_bfloat16*)pWhi,
                           (const __nv_bfloat16*)pWlo, fl_b, pH, N);
    }

    cudaStreamWaitEvent(0, s_join, 0);

    // ---- network: PDL-chained main chain ----
    { cudaLaunchConfig_t c = mkCfg(nodeWarpG, T, 0, 0);
      cudaLaunchKernelEx(&c, agg_kernel<true>,  (const float*)pH, pB, N); }       // h1
    { cudaLaunchConfig_t c = mkCfg(nodeWarpG, T, 0, 0);
      cudaLaunchKernelEx(&c, agg_kernel<false>, (const float*)pB, pC, N); }       // z1
    { cudaLaunchConfig_t c = mkCfg(gemmGrid, T, smem128, 0);                      // h2 = GIN1 MLP
      cudaLaunchKernelEx(&c, gin_mlp, (const float*)pC,
                         (const __nv_bfloat16*)(pWhi + 16384), (const __nv_bfloat16*)(pWlo + 16384), g1_b1,
                         (const __nv_bfloat16*)(pWhi + 2 * 16384), (const __nv_bfloat16*)(pWlo + 2 * 16384), g1_b2,
                         pH, N); }
    { cudaLaunchConfig_t c = mkCfg(nodeWarpG, T, 0, 0);
      cudaLaunchKernelEx(&c, agg_kernel<false>, (const float*)pH, pB, N); }       // z2
    { cudaLaunchConfig_t c = mkCfg(gemmGrid, T, smem128, 0);                      // h3 = GIN2 MLP
      cudaLaunchKernelEx(&c, gin_mlp, (const float*)pB,
                         (const __nv_bfloat16*)(pWhi + 3 * 16384), (const __nv_bfloat16*)(pWlo + 3 * 16384), g2_b1,
                         (const __nv_bfloat16*)(pWhi + 4 * 16384), (const __nv_bfloat16*)(pWlo + 4 * 16384), g2_b2,
                         pC, N); }
    { cudaLaunchConfig_t c = mkCfg(gemmGrid, T, smem64, 0);                       // head + log_softmax
      cudaLaunchKernelEx(&c, gemm_mma<64, false, true, 0>, (const float*)pC,
                         (const __nv_bfloat16*)(pWhi + 5 * 16384), (const __nv_bfloat16*)(pWlo + 5 * 16384), out_b, out, N); }
}

// round 15
// speedup vs baseline: 1.5447x; 1.5447x over previous
#include <cuda_runtime.h>
#include <cuda_bf16.h>
#include <cstdint>
#include <cstddef>

#define MAXN 50000
#define MAXE 600000
#define HDIM 128

// -------------------- scratch --------------------
__device__ float g_h[(size_t)MAXN * HDIM];
__device__ float g_B[(size_t)MAXN * HDIM];
__device__ float g_C[(size_t)MAXN * HDIM];
__device__ int   g_indeg[MAXN];
__device__ int   g_outdeg[MAXN];
__device__ float g_coef[MAXN];
__device__ int   g_start[MAXN];
__device__ int   g_ptr[MAXN];
__device__ int   g_eid[MAXE];
__device__ int   g_blocksum[64];
__device__ __nv_bfloat16 g_Whi[6 * 16384];
__device__ __nv_bfloat16 g_Wlo[6 * 16384];

// -------------------- helpers --------------------
__device__ __forceinline__ uint32_t smem_u32(const void* p) {
    uint32_t a;
    asm("{ .reg .u64 t; cvta.to.shared.u64 t, %1; cvt.u32.u64 %0, t; }" : "=r"(a) : "l"(p));
    return a;
}
__device__ __forceinline__ void ldsm4(uint32_t* r, uint32_t addr) {
    asm volatile("ldmatrix.sync.aligned.m8n8.x4.shared.b16 {%0,%1,%2,%3}, [%4];"
                 : "=r"(r[0]), "=r"(r[1]), "=r"(r[2]), "=r"(r[3]) : "r"(addr));
}
__device__ __forceinline__ void mma_bf16(float* c, const uint32_t* a, uint32_t b0, uint32_t b1) {
    asm volatile("mma.sync.aligned.m16n8k16.row.col.f32.bf16.bf16.f32 "
                 "{%0,%1,%2,%3}, {%4,%5,%6,%7}, {%8,%9}, {%0,%1,%2,%3};"
                 : "+f"(c[0]), "+f"(c[1]), "+f"(c[2]), "+f"(c[3])
                 : "r"(a[0]), "r"(a[1]), "r"(a[2]), "r"(a[3]), "r"(b0), "r"(b1));
}
__device__ __forceinline__ void pdl_wait()   { asm volatile("griddepcontrol.wait;" ::: "memory"); }
__device__ __forceinline__ void pdl_launch() { asm volatile("griddepcontrol.launch_dependents;" ::: "memory"); }

#define RSTRIDE 272
__device__ __forceinline__ uint32_t toff(int r, int k) {
    return (uint32_t)r * RSTRIDE + (uint32_t)k * 2;
}
__device__ __forceinline__ void cvt_store(char* hi, char* lo, uint32_t off, float4 v) {
    __nv_bfloat162 h01 = __floats2bfloat162_rn(v.x, v.y);
    float2 f01 = __bfloat1622float2(h01);
    __nv_bfloat162 l01 = __floats2bfloat162_rn(v.x - f01.x, v.y - f01.y);
    __nv_bfloat162 h23 = __floats2bfloat162_rn(v.z, v.w);
    float2 f23 = __bfloat1622float2(h23);
    __nv_bfloat162 l23 = __floats2bfloat162_rn(v.z - f23.x, v.w - f23.y);
    *(uint32_t*)(hi + off)     = *(uint32_t*)&h01;
    *(uint32_t*)(hi + off + 4) = *(uint32_t*)&h23;
    *(uint32_t*)(lo + off)     = *(uint32_t*)&l01;
    *(uint32_t*)(lo + off + 4) = *(uint32_t*)&l23;
}

// 3-pass merged mainloop over 64x128 A tile (hi/lo) and BNx128 W tile (hi/lo)
template<int NT8>
__device__ __forceinline__ void run_mainloop(
    uint32_t aHi, uint32_t aLo, uint32_t bHi, uint32_t bLo, float acc[2][NT8][4])
{
    #pragma unroll
    for (int mt = 0; mt < 2; mt++)
        #pragma unroll
        for (int nt = 0; nt < NT8; nt++)
            #pragma unroll
            for (int q = 0; q < 4; q++) acc[mt][nt][q] = 0.f;
    #pragma unroll
    for (int ks = 0; ks < 8; ks++) {
        uint32_t afh[8], afl[8];
        ldsm4(afh,     aHi + ks * 32);
        ldsm4(afh + 4, aHi + 16 * RSTRIDE + ks * 32);
        ldsm4(afl,     aLo + ks * 32);
        ldsm4(afl + 4, aLo + 16 * RSTRIDE + ks * 32);
        uint32_t bfh[NT8 * 2], bfl[NT8 * 2];
        #pragma unroll
        for (int nt2 = 0; nt2 < NT8 / 2; nt2++) {
            ldsm4(bfh + nt2 * 4, bHi + nt2 * 16 * RSTRIDE + ks * 32);
            ldsm4(bfl + nt2 * 4, bLo + nt2 * 16 * RSTRIDE + ks * 32);
        }
        #pragma unroll
        for (int mt = 0; mt < 2; mt++)
            #pragma unroll
            for (int nt = 0; nt < NT8; nt++) {
                mma_bf16(acc[mt][nt], afh + mt * 4, bfh[nt * 2], bfh[nt * 2 + 1]);
                mma_bf16(acc[mt][nt], afh + mt * 4, bfl[nt * 2], bfl[nt * 2 + 1]);
                mma_bf16(acc[mt][nt], afl + mt * 4, bfh[nt * 2], bfh[nt * 2 + 1]);
            }
    }
}

// -------------------- weight pre-split --------------------
__global__ void wsplit_kernel(const float* __restrict__ w0, const float* __restrict__ w1,
                              const float* __restrict__ w2, const float* __restrict__ w3,
                              const float* __restrict__ w4, const float* __restrict__ w5)
{
    int i = blockIdx.x * blockDim.x + threadIdx.x;
    int m = i >> 14, off = i & 16383;
    if (m > 5 || (m == 5 && off >= 8192)) return;
    const float* src = (m == 0) ? w0 : (m == 1) ? w1 : (m == 2) ? w2
                     : (m == 3) ? w3 : (m == 4) ? w4 : w5;
    float v = src[off];
    __nv_bfloat16 h = __float2bfloat16_rn(v);
    g_Whi[m * 16384 + off] = h;
    g_Wlo[m * 16384 + off] = __float2bfloat16_rn(v - __bfloat162float(h));
}

// -------------------- single GEMM (BM=64, 2Mx4N warps, 2 CTAs/SM, PDL) -------------------
template<int BN, bool RELU, bool LSM, int PRO>
__global__ __launch_bounds__(256, 2) void gemm_mma(
    const float* __restrict__ A,
    const __nv_bfloat16* __restrict__ Whi, const __nv_bfloat16* __restrict__ Wlo,
    const float* __restrict__ bias, float* __restrict__ C, int M)
{
    constexpr int WN  = BN / 4;
    constexpr int NT8 = WN / 8;
    constexpr int AT  = 64 * RSTRIDE;
    constexpr int WT  = BN * RSTRIDE;
    constexpr int OFF_WHI = 0;
    constexpr int OFF_WLO = WT;
    constexpr int OFF_AHI = 2 * WT;
    constexpr int OFF_ALO = 2 * WT + AT;

    extern __shared__ __align__(16) char smem[];
    const uint32_t sb = smem_u32(smem);
    const int tid = threadIdx.x, wid = tid >> 5, lane = tid & 31;
    const int row0 = blockIdx.x * 64;
    const int warp_m0 = (wid & 1) * 32;
    const int warp_n0 = (wid >> 1) * WN;

    if (PRO == 0) {
        for (int i = tid; i < BN * 16; i += 256) {
            int r = i >> 4, kc = i & 15;
            *(uint4*)(smem + OFF_WHI + toff(r, kc * 8)) = *(const uint4*)(Whi + r * 128 + kc * 8);
            *(uint4*)(smem + OFF_WLO + toff(r, kc * 8)) = *(const uint4*)(Wlo + r * 128 + kc * 8);
        }
        pdl_wait();
        pdl_launch();
        for (int i = tid; i < 64 * 32; i += 256) {
            int r = i >> 5, k = (i & 31) * 4;
            float4 v = make_float4(0.f, 0.f, 0.f, 0.f);
            if (row0 + r < M) v = *(const float4*)(A + (size_t)(row0 + r) * 128 + k);
            cvt_store(smem + OFF_AHI, smem + OFF_ALO, toff(r, k), v);
        }
    } else {
        for (int i = tid; i < 64 * 32; i += 256) {
            int r = i >> 5, k = (i & 31) * 4;
            float4 v = make_float4(0.f, 0.f, 0.f, 0.f);
            if (row0 + r < M) v = *(const float4*)(A + (size_t)(row0 + r) * 128 + k);
            cvt_store(smem + OFF_AHI, smem + OFF_ALO, toff(r, k), v);
        }
        pdl_wait();
        pdl_launch();
        for (int i = tid; i < BN * 16; i += 256) {
            int r = i >> 4, kc = i & 15;
            *(uint4*)(smem + OFF_WHI + toff(r, kc * 8)) = *(const uint4*)(Whi + r * 128 + kc * 8);
            *(uint4*)(smem + OFF_WLO + toff(r, kc * 8)) = *(const uint4*)(Wlo + r * 128 + kc * 8);
        }
    }
    __syncthreads();

    const uint32_t aoff = (uint32_t)(warp_m0 + (lane & 15)) * RSTRIDE + (uint32_t)((lane >> 4) * 8) * 2;
    const int brow = (lane & 7) + (lane >> 4) * 8;
    const int bk   = ((lane >> 3) & 1) * 8;
    const uint32_t boff = (uint32_t)(warp_n0 + brow) * RSTRIDE + (uint32_t)bk * 2;

    float acc[2][NT8][4];
    run_mainloop<NT8>(sb + OFF_AHI + aoff, sb + OFF_ALO + aoff,
                      sb + OFF_WHI + boff, sb + OFF_WLO + boff, acc);

    const int colq = (lane & 3) * 2;
    if (!LSM) {
        #pragma unroll
        for (int mt = 0; mt < 2; mt++) {
            int r0 = row0 + warp_m0 + mt * 16 + (lane >> 2);
            #pragma unroll
            for (int nt = 0; nt < NT8; nt++) {
                int col = warp_n0 + nt * 8 + colq;
                float2 b2 = *(const float2*)(bias + col);
                float2 o0, o1;
                o0.x = acc[mt][nt][0] + b2.x; o0.y = acc[mt][nt][1] + b2.y;
                o1.x = acc[mt][nt][2] + b2.x; o1.y = acc[mt][nt][3] + b2.y;
                if (RELU) {
                    o0.x = fmaxf(o0.x, 0.f); o0.y = fmaxf(o0.y, 0.f);
                    o1.x = fmaxf(o1.x, 0.f); o1.y = fmaxf(o1.y, 0.f);
                }
                if (r0 < M)     *(float2*)(C + (size_t)r0 * BN + col)       = o0;
                if (r0 + 8 < M) *(float2*)(C + (size_t)(r0 + 8) * BN + col) = o1;
            }
        }
    } else {
        __syncthreads();
        float* Cs = (float*)smem;  // [64][68]
        #pragma unroll
        for (int mt = 0; mt < 2; mt++) {
            int rr = warp_m0 + mt * 16 + (lane >> 2);
            #pragma unroll
            for (int nt = 0; nt < NT8; nt++) {
                int col = warp_n0 + nt * 8 + colq;
                float2 b2 = *(const float2*)(bias + col);
                Cs[rr * 68 + col]            = acc[mt][nt][0] + b2.x;
                Cs[rr * 68 + col + 1]        = acc[mt][nt][1] + b2.y;
                Cs[(rr + 8) * 68 + col]      = acc[mt][nt][2] + b2.x;
                Cs[(rr + 8) * 68 + col + 1]  = acc[mt][nt][3] + b2.y;
            }
        }
        __syncthreads();
        #pragma unroll
        for (int it = 0; it < 8; it++) {
            int r = wid + it * 8;
            float2 v = *(float2*)&Cs[r * 68 + lane * 2];
            float m = fmaxf(v.x, v.y);
            #pragma unroll
            for (int o = 16; o; o >>= 1) m = fmaxf(m, __shfl_xor_sync(0xffffffffu, m, o));
            float s = expf(v.x - m) + expf(v.y - m);
            #pragma unroll
            for (int o = 16; o; o >>= 1) s += __shfl_xor_sync(0xffffffffu, s, o);
            float ls = logf(s) + m;
            int gr = row0 + r;
            if (gr < M)
                *(float2*)(C + (size_t)gr * 64 + lane * 2) = make_float2(v.x - ls, v.y - ls);
        }
    }
}

// -------------------- fused GIN MLP: C = relu( relu(A W1^T + b1) W2^T + b2 ) --------------
__global__ __launch_bounds__(256, 2) void gin_mlp(
    const float* __restrict__ A,
    const __nv_bfloat16* __restrict__ W1hi, const __nv_bfloat16* __restrict__ W1lo,
    const float* __restrict__ b1,
    const __nv_bfloat16* __restrict__ W2hi, const __nv_bfloat16* __restrict__ W2lo,
    const float* __restrict__ b2, float* __restrict__ C, int M)
{
    constexpr int NT8 = 4;
    constexpr int AT  = 64 * RSTRIDE;
    constexpr int WT  = 128 * RSTRIDE;
    constexpr int OFF_WHI = 0;
    constexpr int OFF_WLO = WT;
    constexpr int OFF_AHI = 2 * WT;
    constexpr int OFF_ALO = 2 * WT + AT;

    extern __shared__ __align__(16) char smem[];
    const uint32_t sb = smem_u32(smem);
    const int tid = threadIdx.x, wid = tid >> 5, lane = tid & 31;
    const int row0 = blockIdx.x * 64;
    const int warp_m0 = (wid & 1) * 32;
    const int warp_n0 = (wid >> 1) * 32;

    for (int i = tid; i < 128 * 16; i += 256) {
        int r = i >> 4, kc = i & 15;
        *(uint4*)(smem + OFF_WHI + toff(r, kc * 8)) = *(const uint4*)(W1hi + r * 128 + kc * 8);
        *(uint4*)(smem + OFF_WLO + toff(r, kc * 8)) = *(const uint4*)(W1lo + r * 128 + kc * 8);
    }
    pdl_wait();
    pdl_launch();
    for (int i = tid; i < 64 * 32; i += 256) {
        int r = i >> 5, k = (i & 31) * 4;
        float4 v = make_float4(0.f, 0.f, 0.f, 0.f);
        if (row0 + r < M) v = *(const float4*)(A + (size_t)(row0 + r) * 128 + k);
        cvt_store(smem + OFF_AHI, smem + OFF_ALO, toff(r, k), v);
    }
    __syncthreads();

    const uint32_t aoff = (uint32_t)(warp_m0 + (lane & 15)) * RSTRIDE + (uint32_t)((lane >> 4) * 8) * 2;
    const int brow = (lane & 7) + (lane >> 4) * 8;
    const int bk   = ((lane >> 3) & 1) * 8;
    const uint32_t boff = (uint32_t)(warp_n0 + brow) * RSTRIDE + (uint32_t)bk * 2;
    const uint32_t aHi = sb + OFF_AHI + aoff, aLo = sb + OFF_ALO + aoff;
    const uint32_t bHi = sb + OFF_WHI + boff, bLo = sb + OFF_WLO + boff;

    float acc[2][NT8][4];
    run_mainloop<NT8>(aHi, aLo, bHi, bLo, acc);
    __syncthreads();

    const int colq = (lane & 3) * 2;
    #pragma unroll
    for (int mt = 0; mt < 2; mt++) {
        int rr = warp_m0 + mt * 16 + (lane >> 2);
        #pragma unroll
        for (int nt = 0; nt < NT8; nt++) {
            int col = warp_n0 + nt * 8 + colq;
            float2 bb = *(const float2*)(b1 + col);
            float z0 = fmaxf(acc[mt][nt][0] + bb.x, 0.f);
            float z1 = fmaxf(acc[mt][nt][1] + bb.y, 0.f);
            float z2 = fmaxf(acc[mt][nt][2] + bb.x, 0.f);
            float z3 = fmaxf(acc[mt][nt][3] + bb.y, 0.f);
            __nv_bfloat162 h0 = __floats2bfloat162_rn(z0, z1);
            float2 f0 = __bfloat1622float2(h0);
            __nv_bfloat162 l0 = __floats2bfloat162_rn(z0 - f0.x, z1 - f0.y);
            __nv_bfloat162 h1 = __floats2bfloat162_rn(z2, z3);
            float2 f1 = __bfloat1622float2(h1);
            __nv_bfloat162 l1 = __floats2bfloat162_rn(z2 - f1.x, z3 - f1.y);
            *(uint32_t*)(smem + OFF_AHI + toff(rr, col))     = *(uint32_t*)&h0;
            *(uint32_t*)(smem + OFF_ALO + toff(rr, col))     = *(uint32_t*)&l0;
            *(uint32_t*)(smem + OFF_AHI + toff(rr + 8, col)) = *(uint32_t*)&h1;
            *(uint32_t*)(smem + OFF_ALO + toff(rr + 8, col)) = *(uint32_t*)&l1;
        }
    }
    for (int i = tid; i < 128 * 16; i += 256) {
        int r = i >> 4, kc = i & 15;
        *(uint4*)(smem + OFF_WHI + toff(r, kc * 8)) = *(const uint4*)(W2hi + r * 128 + kc * 8);
        *(uint4*)(smem + OFF_WLO + toff(r, kc * 8)) = *(const uint4*)(W2lo + r * 128 + kc * 8);
    }
    __syncthreads();

    run_mainloop<NT8>(aHi, aLo, bHi, bLo, acc);

    #pragma unroll
    for (int mt = 0; mt < 2; mt++) {
        int r0 = row0 + warp_m0 + mt * 16 + (lane >> 2);
        #pragma unroll
        for (int nt = 0; nt < NT8; nt++) {
            int col = warp_n0 + nt * 8 + colq;
            float2 bb = *(const float2*)(b2 + col);
            float2 o0, o1;
            o0.x = fmaxf(acc[mt][nt][0] + bb.x, 0.f);
            o0.y = fmaxf(acc[mt][nt][1] + bb.y, 0.f);
            o1.x = fmaxf(acc[mt][nt][2] + bb.x, 0.f);
            o1.y = fmaxf(acc[mt][nt][3] + bb.y, 0.f);
            if (r0 < M)     *(float2*)(C + (size_t)r0 * 128 + col)       = o0;
            if (r0 + 8 < M) *(float2*)(C + (size_t)(r0 + 8) * 128 + col) = o1;
        }
    }
}

// -------------------- CSR build (R13 structure, PDL-chained) --------------------
__global__ void zero_deg_kernel(int n) {
    pdl_launch();
    int i = blockIdx.x * blockDim.x + threadIdx.x;
    if (i < n) { g_indeg[i] = 0; g_outdeg[i] = 0; }
}
__global__ void hist_kernel(const int* __restrict__ row, const int* __restrict__ col, int E) {
    int e = blockIdx.x * blockDim.x + threadIdx.x;
    int r = 0, c = 0;
    if (e < E) { r = row[e]; c = col[e]; }
    pdl_wait();
    pdl_launch();
    if (e < E) {
        atomicAdd(&g_indeg[c], 1);
        atomicAdd(&g_outdeg[r], 1);
    }
}
__global__ __launch_bounds__(1024) void scan_block_kernel(int* __restrict__ out, int n) {
    __shared__ int wsum[32];
    pdl_wait();
    pdl_launch();
    int i = blockIdx.x * 1024 + threadIdx.x;
    int lane = threadIdx.x & 31, wid = threadIdx.x >> 5;
    int orig = (i < n) ? g_indeg[i] : 0;
    int v = orig;
    #pragma unroll
    for (int o = 1; o < 32; o <<= 1) {
        int t = __shfl_up_sync(0xffffffffu, v, o);
        if (lane >= o) v += t;
    }
    if (lane == 31) wsum[wid] = v;
    __syncthreads();
    if (wid == 0) {
        int s = wsum[lane];
        #pragma unroll
        for (int o = 1; o < 32; o <<= 1) {
            int t = __shfl_up_sync(0xffffffffu, s, o);
            if (lane >= o) s += t;
        }
        wsum[lane] = s;
    }
    __syncthreads();
    int excl = v - orig + (wid > 0 ? wsum[wid - 1] : 0);
    if (i < n) out[i] = excl;
    if (threadIdx.x == 1023) g_blocksum[blockIdx.x] = excl + orig;
}
__global__ void scan_top_kernel(int nb) {
    __shared__ int ws[2];
    pdl_wait();
    pdl_launch();
    int t = threadIdx.x, lane = t & 31, w = t >> 5;
    int v = (t < nb) ? g_blocksum[t] : 0;
    int s = v;
    #pragma unroll
    for (int o = 1; o < 32; o <<= 1) {
        int x = __shfl_up_sync(0xffffffffu, s, o);
        if (lane >= o) s += x;
    }
    if (lane == 31) ws[w] = s;
    __syncthreads();
    int excl = s - v + (w == 1 ? ws[0] : 0);
    if (t < nb) g_blocksum[t] = excl;
}
__global__ void finalize_kernel(const int* __restrict__ partial, int n) {
    pdl_wait();
    pdl_launch();
    int i = blockIdx.x * blockDim.x + threadIdx.x;
    if (i >= n) return;
    int s = partial[i] + g_blocksum[i >> 10];
    g_start[i] = s;
    g_ptr[i]   = s;
    g_coef[i]  = 1.0f / (float)(g_outdeg[i] + 1);
}
__global__ void scatter_kernel(const int* __restrict__ row, const int* __restrict__ col, int E) {
    int e = blockIdx.x * blockDim.x + threadIdx.x;
    int r = 0, c = 0;
    if (e < E) { r = row[e]; c = col[e]; }
    pdl_wait();
    pdl_launch();
    if (e < E) {
        int p = atomicAdd(&g_ptr[c], 1);
        g_eid[p] = r;
    }
}

// -------------------- gather aggregation (fp32, 2-deep pipelined, PDL) ------------------
template<bool ATT>
__global__ void agg_kernel(const float* __restrict__ src, float* __restrict__ dst, int n) {
    int node = (blockIdx.x * blockDim.x + threadIdx.x) >> 5;
    int lane = threadIdx.x & 31;
    if (node >= n) { pdl_wait(); pdl_launch(); return; }
    int s = g_start[node], e = s + g_indeg[node];
    float cself = ATT ? g_coef[node] : 1.0f;
    int myeid = (s + lane < e) ? __ldg(&g_eid[s + lane]) : 0;
    pdl_wait();
    pdl_launch();
    float4 acc = *(const float4*)(src + (size_t)node * 128 + lane * 4);
    if (ATT) { acc.x *= cself; acc.y *= cself; acc.z *= cself; acc.w *= cself; }
    float4 acc2 = make_float4(0.f, 0.f, 0.f, 0.f);
    for (int j0 = s; j0 < e; j0 += 32) {
        int nb = min(32, e - j0);
        int cur = myeid;
        int jn = j0 + 32;
        if (jn < e) myeid = (jn + lane < e) ? __ldg(&g_eid[jn + lane]) : 0;
        int t = 0;
        for (; t + 1 < nb; t += 2) {
            int r0 = __shfl_sync(0xffffffffu, cur, t);
            int r1 = __shfl_sync(0xffffffffu, cur, t + 1);
            float4 v0 = *(const float4*)(src + (size_t)r0 * 128 + lane * 4);
            float4 v1 = *(const float4*)(src + (size_t)r1 * 128 + lane * 4);
            float c0 = ATT ? g_coef[r0] : 1.0f;
            float c1 = ATT ? g_coef[r1] : 1.0f;
            acc.x  = fmaf(c0, v0.x, acc.x);  acc.y  = fmaf(c0, v0.y, acc.y);
            acc.z  = fmaf(c0, v0.z, acc.z);  acc.w  = fmaf(c0, v0.w, acc.w);
            acc2.x = fmaf(c1, v1.x, acc2.x); acc2.y = fmaf(c1, v1.y, acc2.y);
            acc2.z = fmaf(c1, v1.z, acc2.z); acc2.w = fmaf(c1, v1.w, acc2.w);
        }
        if (t < nb) {
            int r0 = __shfl_sync(0xffffffffu, cur, t);
            float4 v0 = *(const float4*)(src + (size_t)r0 * 128 + lane * 4);
            float c0 = ATT ? g_coef[r0] : 1.0f;
            acc.x = fmaf(c0, v0.x, acc.x); acc.y = fmaf(c0, v0.y, acc.y);
            acc.z = fmaf(c0, v0.z, acc.z); acc.w = fmaf(c0, v0.w, acc.w);
        }
    }
    acc.x += acc2.x; acc.y += acc2.y; acc.z += acc2.z; acc.w += acc2.w;
    if (ATT) {
        acc.x = fmaxf(acc.x, 0.f); acc.y = fmaxf(acc.y, 0.f);
        acc.z = fmaxf(acc.z, 0.f); acc.w = fmaxf(acc.w, 0.f);
    }
    *(float4*)(dst + (size_t)node * 128 + lane * 4) = acc;
}

// -------------------- launch --------------------
extern "C" void kernel_launch(void* const* d_in, const int* in_sizes, int n_in,
                              void* d_out, int out_size)
{
    const float* x     = (const float*)d_in[0];
    const int*   ei    = (const int*)  d_in[1];
    const float* fl_W  = (const float*)d_in[2];
    const float* fl_b  = (const float*)d_in[3];
    // d_in[4] = fl_att : softmax over identical per-segment logits is uniform -> unused
    const float* g1_W1 = (const float*)d_in[5];
    const float* g1_b1 = (const float*)d_in[6];
    const float* g1_W2 = (const float*)d_in[7];
    const float* g1_b2 = (const float*)d_in[8];
    const float* g2_W1 = (const float*)d_in[9];
    const float* g2_b1 = (const float*)d_in[10];
    const float* g2_W2 = (const float*)d_in[11];
    const float* g2_b2 = (const float*)d_in[12];
    const float* out_W = (const float*)d_in[13];
    const float* out_b = (const float*)d_in[14];
    float* out = (float*)d_out;

    const int N = in_sizes[0] / HDIM;
    const int E = in_sizes[1] / 2;
    const int* row = ei;
    const int* col = ei + E;

    float *pH = nullptr, *pB = nullptr, *pC = nullptr;
    int* pPtr = nullptr;
    __nv_bfloat16 *pWhi = nullptr, *pWlo = nullptr;
    cudaGetSymbolAddress((void**)&pH, g_h);
    cudaGetSymbolAddress((void**)&pB, g_B);
    cudaGetSymbolAddress((void**)&pC, g_C);
    cudaGetSymbolAddress((void**)&pPtr, g_ptr);
    cudaGetSymbolAddress((void**)&pWhi, g_Whi);
    cudaGetSymbolAddress((void**)&pWlo, g_Wlo);

    const int smem128 = 2 * 128 * RSTRIDE + 2 * 64 * RSTRIDE;  // 104448
    const int smem64  = 4 * 64 * RSTRIDE;                      // 69632
    cudaFuncSetAttribute(gemm_mma<128, false, false, 1>, cudaFuncAttributeMaxDynamicSharedMemorySize, smem128);
    cudaFuncSetAttribute(gin_mlp,                        cudaFuncAttributeMaxDynamicSharedMemorySize, smem128);
    cudaFuncSetAttribute(gemm_mma<64,  false, true,  0>, cudaFuncAttributeMaxDynamicSharedMemorySize, smem64);

    static cudaStream_t s_side = [] {
        cudaStream_t s; cudaStreamCreateWithFlags(&s, cudaStreamNonBlocking); return s;
    }();
    static cudaEvent_t s_fork = [] {
        cudaEvent_t e; cudaEventCreateWithFlags(&e, cudaEventDisableTiming); return e;
    }();
    static cudaEvent_t s_join = [] {
        cudaEvent_t e; cudaEventCreateWithFlags(&e, cudaEventDisableTiming); return e;
    }();

    const int T = 256;
    const int gemmGrid  = (N + 63) / 64;
    const int edgeThG   = (E + T - 1) / T;
    const int nodeThG   = (N + T - 1) / T;
    const int nodeWarpG = (N * 32 + T - 1) / T;
    const int scanBlocks = (N + 1023) / 1024;

    cudaLaunchAttribute pdlAttr[1];
    pdlAttr[0].id = cudaLaunchAttributeProgrammaticStreamSerialization;
    pdlAttr[0].val.programmaticStreamSerializationAllowed = 1;
    auto mkCfg = [&](int grid, int blk, int smem, cudaStream_t st) {
        cudaLaunchConfig_t c = {};
        c.gridDim = dim3(grid); c.blockDim = dim3(blk);
        c.dynamicSmemBytes = (size_t)smem; c.stream = st;
        c.attrs = pdlAttr; c.numAttrs = 1;
        return c;
    };

    // ---- fork: CSR build on side stream (PDL-chained, R13 scan structure) ----
    cudaEventRecord(s_fork, 0);
    cudaStreamWaitEvent(s_side, s_fork, 0);

    { cudaLaunchConfig_t c = mkCfg(nodeThG, T, 0, s_side);
      cudaLaunchKernelEx(&c, zero_deg_kernel, N); }
    { cudaLaunchConfig_t c = mkCfg(edgeThG, T, 0, s_side);
      cudaLaunchKernelEx(&c, hist_kernel, row, col, E); }
    { cudaLaunchConfig_t c = mkCfg(scanBlocks, 1024, 0, s_side);
      cudaLaunchKernelEx(&c, scan_block_kernel, pPtr, N); }
    { cudaLaunchConfig_t c = mkCfg(1, 64, 0, s_side);
      cudaLaunchKernelEx(&c, scan_top_kernel, scanBlocks); }
    { cudaLaunchConfig_t c = mkCfg(nodeThG, T, 0, s_side);
      cudaLaunchKernelEx(&c, finalize_kernel, (const int*)pPtr, N); }
    { cudaLaunchConfig_t c = mkCfg(edgeThG, T, 0, s_side);
      cudaLaunchKernelEx(&c, scatter_kernel, row, col, E); }
    cudaEventRecord(s_join, s_side);

    wsplit_kernel<<<(6 * 16384 + T - 1) / T, T>>>(fl_W, g1_W1, g1_W2, g2_W1, g2_W2, out_W);
    {   // gemm1: stage A(x) during wsplit tail (PRO=1)
        cudaLaunchConfig_t c = mkCfg(gemmGrid, T, smem128, 0);
        cudaLaunchKernelEx(&c, gemm_mma<128, false, false, 1>, x, (const __nv_bfloat16*)pWhi,
                           (const __nv_bfloat16*)pWlo, fl_b, pH, N);
    }

    cudaStreamWaitEvent(0, s_join, 0);

    // ---- network: PDL-chained main chain ----
    { cudaLaunchConfig_t c = mkCfg(nodeWarpG, T, 0, 0);
      cudaLaunchKernelEx(&c, agg_kernel<true>,  (const float*)pH, pB, N); }       // h1
    { cudaLaunchConfig_t c = mkCfg(nodeWarpG, T, 0, 0);
      cudaLaunchKernelEx(&c, agg_kernel<false>, (const float*)pB, pC, N); }       // z1
    { cudaLaunchConfig_t c = mkCfg(gemmGrid, T, smem128, 0);                      // h2 = GIN1 MLP
      cudaLaunchKernelEx(&c, gin_mlp, (const float*)pC,
                         (const __nv_bfloat16*)(pWhi + 16384), (const __nv_bfloat16*)(pWlo + 16384), g1_b1,
                         (const __nv_bfloat16*)(pWhi + 2 * 16384), (const __nv_bfloat16*)(pWlo + 2 * 16384), g1_b2,
                         pH, N); }
    { cudaLaunchConfig_t c = mkCfg(nodeWarpG, T, 0, 0);
      cudaLaunchKernelEx(&c, agg_kernel<false>, (const float*)pH, pB, N); }       // z2
    { cudaLaunchConfig_t c = mkCfg(gemmGrid, T, smem128, 0);                      // h3 = GIN2 MLP
      cudaLaunchKernelEx(&c, gin_mlp, (const float*)pB,
                         (const __nv_bfloat16*)(pWhi + 3 * 16384), (const __nv_bfloat16*)(pWlo + 3 * 16384), g2_b1,
                         (const __nv_bfloat16*)(pWhi + 4 * 16384), (const __nv_bfloat16*)(pWlo + 4 * 16384), g2_b2,
                         pC, N); }
    { cudaLaunchConfig_t c = mkCfg(gemmGrid, T, smem64, 0);                       // head + log_softmax
      cudaLaunchKernelEx(&c, gemm_mma<64, false, true, 0>, (const float*)pC,
                         (const __nv_bfloat16*)(pWhi + 5 * 16384), (const __nv_bfloat16*)(pWlo + 5 * 16384), out_b, out, N); }
}

// round 16
// speedup vs baseline: 1.6068x; 1.0402x over previous
#include <cuda_runtime.h>
#include <cuda_bf16.h>
#include <cstdint>
#include <cstddef>

#define MAXN 50000
#define MAXE 600000
#define HDIM 128

// -------------------- scratch --------------------
__device__ float g_h[(size_t)MAXN * HDIM];
__device__ float g_B[(size_t)MAXN * HDIM];
__device__ float g_C[(size_t)MAXN * HDIM];
__device__ int   g_indeg[MAXN];
__device__ int   g_outdeg[MAXN];
__device__ float g_coef[MAXN];
__device__ int   g_start[MAXN];
__device__ int   g_ptr[MAXN];
__device__ int   g_eid[MAXE];
__device__ int   g_blocksum[64];
__device__ __nv_bfloat16 g_Whi[6 * 16384];
__device__ __nv_bfloat16 g_Wlo[6 * 16384];

// -------------------- helpers --------------------
__device__ __forceinline__ uint32_t smem_u32(const void* p) {
    uint32_t a;
    asm("{ .reg .u64 t; cvta.to.shared.u64 t, %1; cvt.u32.u64 %0, t; }" : "=r"(a) : "l"(p));
    return a;
}
__device__ __forceinline__ void ldsm4(uint32_t* r, uint32_t addr) {
    asm volatile("ldmatrix.sync.aligned.m8n8.x4.shared.b16 {%0,%1,%2,%3}, [%4];"
                 : "=r"(r[0]), "=r"(r[1]), "=r"(r[2]), "=r"(r[3]) : "r"(addr));
}
__device__ __forceinline__ void mma_bf16(float* c, const uint32_t* a, uint32_t b0, uint32_t b1) {
    asm volatile("mma.sync.aligned.m16n8k16.row.col.f32.bf16.bf16.f32 "
                 "{%0,%1,%2,%3}, {%4,%5,%6,%7}, {%8,%9}, {%0,%1,%2,%3};"
                 : "+f"(c[0]), "+f"(c[1]), "+f"(c[2]), "+f"(c[3])
                 : "r"(a[0]), "r"(a[1]), "r"(a[2]), "r"(a[3]), "r"(b0), "r"(b1));
}
__device__ __forceinline__ void pdl_wait()   { asm volatile("griddepcontrol.wait;" ::: "memory"); }
__device__ __forceinline__ void pdl_launch() { asm volatile("griddepcontrol.launch_dependents;" ::: "memory"); }

#define RSTRIDE 272
__device__ __forceinline__ uint32_t toff(int r, int k) {
    return (uint32_t)r * RSTRIDE + (uint32_t)k * 2;
}
__device__ __forceinline__ void cvt_store(char* hi, char* lo, uint32_t off, float4 v) {
    __nv_bfloat162 h01 = __floats2bfloat162_rn(v.x, v.y);
    float2 f01 = __bfloat1622float2(h01);
    __nv_bfloat162 l01 = __floats2bfloat162_rn(v.x - f01.x, v.y - f01.y);
    __nv_bfloat162 h23 = __floats2bfloat162_rn(v.z, v.w);
    float2 f23 = __bfloat1622float2(h23);
    __nv_bfloat162 l23 = __floats2bfloat162_rn(v.z - f23.x, v.w - f23.y);
    *(uint32_t*)(hi + off)     = *(uint32_t*)&h01;
    *(uint32_t*)(hi + off + 4) = *(uint32_t*)&h23;
    *(uint32_t*)(lo + off)     = *(uint32_t*)&l01;
    *(uint32_t*)(lo + off + 4) = *(uint32_t*)&l23;
}

// 3-pass merged mainloop over 64x128 A tile (hi/lo) and (NT8*8 x128) W tile (hi/lo)
template<int NT8>
__device__ __forceinline__ void run_mainloop(
    uint32_t aHi, uint32_t aLo, uint32_t bHi, uint32_t bLo, float acc[2][NT8][4])
{
    #pragma unroll
    for (int mt = 0; mt < 2; mt++)
        #pragma unroll
        for (int nt = 0; nt < NT8; nt++)
            #pragma unroll
            for (int q = 0; q < 4; q++) acc[mt][nt][q] = 0.f;
    #pragma unroll
    for (int ks = 0; ks < 8; ks++) {
        uint32_t afh[8], afl[8];
        ldsm4(afh,     aHi + ks * 32);
        ldsm4(afh + 4, aHi + 16 * RSTRIDE + ks * 32);
        ldsm4(afl,     aLo + ks * 32);
        ldsm4(afl + 4, aLo + 16 * RSTRIDE + ks * 32);
        uint32_t bfh[NT8 * 2], bfl[NT8 * 2];
        #pragma unroll
        for (int nt2 = 0; nt2 < NT8 / 2; nt2++) {
            ldsm4(bfh + nt2 * 4, bHi + nt2 * 16 * RSTRIDE + ks * 32);
            ldsm4(bfl + nt2 * 4, bLo + nt2 * 16 * RSTRIDE + ks * 32);
        }
        #pragma unroll
        for (int mt = 0; mt < 2; mt++)
            #pragma unroll
            for (int nt = 0; nt < NT8; nt++) {
                mma_bf16(acc[mt][nt], afh + mt * 4, bfh[nt * 2], bfh[nt * 2 + 1]);
                mma_bf16(acc[mt][nt], afh + mt * 4, bfl[nt * 2], bfl[nt * 2 + 1]);
                mma_bf16(acc[mt][nt], afl + mt * 4, bfh[nt * 2], bfh[nt * 2 + 1]);
            }
    }
}

// -------------------- weight pre-split --------------------
__global__ void wsplit_kernel(const float* __restrict__ w0, const float* __restrict__ w1,
                              const float* __restrict__ w2, const float* __restrict__ w3,
                              const float* __restrict__ w4, const float* __restrict__ w5)
{
    int i = blockIdx.x * blockDim.x + threadIdx.x;
    int m = i >> 14, off = i & 16383;
    if (m > 5 || (m == 5 && off >= 8192)) return;
    const float* src = (m == 0) ? w0 : (m == 1) ? w1 : (m == 2) ? w2
                     : (m == 3) ? w3 : (m == 4) ? w4 : w5;
    float v = src[off];
    __nv_bfloat16 h = __float2bfloat16_rn(v);
    g_Whi[m * 16384 + off] = h;
    g_Wlo[m * 16384 + off] = __float2bfloat16_rn(v - __bfloat162float(h));
}

// -------------------- single GEMM (BM=64, 2Mx4N warps, 2 CTAs/SM, PDL) -------------------
// PRO==1: predecessor produces W (wsplit) -> stage A first.
template<int BN, bool RELU, int PRO>
__global__ __launch_bounds__(256, 2) void gemm_mma(
    const float* __restrict__ A,
    const __nv_bfloat16* __restrict__ Whi, const __nv_bfloat16* __restrict__ Wlo,
    const float* __restrict__ bias, float* __restrict__ C, int M)
{
    constexpr int WN  = BN / 4;
    constexpr int NT8 = WN / 8;
    constexpr int AT  = 64 * RSTRIDE;
    constexpr int WT  = BN * RSTRIDE;
    constexpr int OFF_WHI = 0;
    constexpr int OFF_WLO = WT;
    constexpr int OFF_AHI = 2 * WT;
    constexpr int OFF_ALO = 2 * WT + AT;

    extern __shared__ __align__(16) char smem[];
    const uint32_t sb = smem_u32(smem);
    const int tid = threadIdx.x, wid = tid >> 5, lane = tid & 31;
    const int row0 = blockIdx.x * 64;
    const int warp_m0 = (wid & 1) * 32;
    const int warp_n0 = (wid >> 1) * WN;

    if (PRO == 0) {
        for (int i = tid; i < BN * 16; i += 256) {
            int r = i >> 4, kc = i & 15;
            *(uint4*)(smem + OFF_WHI + toff(r, kc * 8)) = *(const uint4*)(Whi + r * 128 + kc * 8);
            *(uint4*)(smem + OFF_WLO + toff(r, kc * 8)) = *(const uint4*)(Wlo + r * 128 + kc * 8);
        }
        pdl_wait();
        pdl_launch();
        for (int i = tid; i < 64 * 32; i += 256) {
            int r = i >> 5, k = (i & 31) * 4;
            float4 v = make_float4(0.f, 0.f, 0.f, 0.f);
            if (row0 + r < M) v = *(const float4*)(A + (size_t)(row0 + r) * 128 + k);
            cvt_store(smem + OFF_AHI, smem + OFF_ALO, toff(r, k), v);
        }
    } else {
        for (int i = tid; i < 64 * 32; i += 256) {
            int r = i >> 5, k = (i & 31) * 4;
            float4 v = make_float4(0.f, 0.f, 0.f, 0.f);
            if (row0 + r < M) v = *(const float4*)(A + (size_t)(row0 + r) * 128 + k);
            cvt_store(smem + OFF_AHI, smem + OFF_ALO, toff(r, k), v);
        }
        pdl_wait();
        pdl_launch();
        for (int i = tid; i < BN * 16; i += 256) {
            int r = i >> 4, kc = i & 15;
            *(uint4*)(smem + OFF_WHI + toff(r, kc * 8)) = *(const uint4*)(Whi + r * 128 + kc * 8);
            *(uint4*)(smem + OFF_WLO + toff(r, kc * 8)) = *(const uint4*)(Wlo + r * 128 + kc * 8);
        }
    }
    __syncthreads();

    const uint32_t aoff = (uint32_t)(warp_m0 + (lane & 15)) * RSTRIDE + (uint32_t)((lane >> 4) * 8) * 2;
    const int brow = (lane & 7) + (lane >> 4) * 8;
    const int bk   = ((lane >> 3) & 1) * 8;
    const uint32_t boff = (uint32_t)(warp_n0 + brow) * RSTRIDE + (uint32_t)bk * 2;

    float acc[2][NT8][4];
    run_mainloop<NT8>(sb + OFF_AHI + aoff, sb + OFF_ALO + aoff,
                      sb + OFF_WHI + boff, sb + OFF_WLO + boff, acc);

    const int colq = (lane & 3) * 2;
    #pragma unroll
    for (int mt = 0; mt < 2; mt++) {
        int r0 = row0 + warp_m0 + mt * 16 + (lane >> 2);
        #pragma unroll
        for (int nt = 0; nt < NT8; nt++) {
            int col = warp_n0 + nt * 8 + colq;
            float2 b2 = *(const float2*)(bias + col);
            float2 o0, o1;
            o0.x = acc[mt][nt][0] + b2.x; o0.y = acc[mt][nt][1] + b2.y;
            o1.x = acc[mt][nt][2] + b2.x; o1.y = acc[mt][nt][3] + b2.y;
            if (RELU) {
                o0.x = fmaxf(o0.x, 0.f); o0.y = fmaxf(o0.y, 0.f);
                o1.x = fmaxf(o1.x, 0.f); o1.y = fmaxf(o1.y, 0.f);
            }
            if (r0 < M)     *(float2*)(C + (size_t)r0 * BN + col)       = o0;
            if (r0 + 8 < M) *(float2*)(C + (size_t)(r0 + 8) * BN + col) = o1;
        }
    }
}

// -------------------- fused GIN MLP (+ optional head+log_softmax third stage) ------------
// HEAD=false: C[M,128] = relu( relu(A W1^T + b1) W2^T + b2 )
// HEAD=true : out[M,64] = log_softmax( relu(relu(A W1^T+b1) W2^T+b2) Wh^T + bh )
template<bool HEAD>
__global__ __launch_bounds__(256, 2) void gin_mlp(
    const float* __restrict__ A,
    const __nv_bfloat16* __restrict__ W1hi, const __nv_bfloat16* __restrict__ W1lo,
    const float* __restrict__ b1,
    const __nv_bfloat16* __restrict__ W2hi, const __nv_bfloat16* __restrict__ W2lo,
    const float* __restrict__ b2,
    const __nv_bfloat16* __restrict__ Whhi, const __nv_bfloat16* __restrict__ Whlo,
    const float* __restrict__ bh,
    float* __restrict__ C, int M)
{
    constexpr int NT8 = 4;
    constexpr int AT  = 64 * RSTRIDE;
    constexpr int WT  = 128 * RSTRIDE;
    constexpr int OFF_WHI = 0;
    constexpr int OFF_WLO = WT;
    constexpr int OFF_AHI = 2 * WT;
    constexpr int OFF_ALO = 2 * WT + AT;

    extern __shared__ __align__(16) char smem[];
    const uint32_t sb = smem_u32(smem);
    const int tid = threadIdx.x, wid = tid >> 5, lane = tid & 31;
    const int row0 = blockIdx.x * 64;
    const int warp_m0 = (wid & 1) * 32;
    const int warp_n0 = (wid >> 1) * 32;

    // stage W1 (predecessor-independent), wait, stage A
    for (int i = tid; i < 128 * 16; i += 256) {
        int r = i >> 4, kc = i & 15;
        *(uint4*)(smem + OFF_WHI + toff(r, kc * 8)) = *(const uint4*)(W1hi + r * 128 + kc * 8);
        *(uint4*)(smem + OFF_WLO + toff(r, kc * 8)) = *(const uint4*)(W1lo + r * 128 + kc * 8);
    }
    pdl_wait();
    pdl_launch();
    for (int i = tid; i < 64 * 32; i += 256) {
        int r = i >> 5, k = (i & 31) * 4;
        float4 v = make_float4(0.f, 0.f, 0.f, 0.f);
        if (row0 + r < M) v = *(const float4*)(A + (size_t)(row0 + r) * 128 + k);
        cvt_store(smem + OFF_AHI, smem + OFF_ALO, toff(r, k), v);
    }
    __syncthreads();

    const uint32_t aoff = (uint32_t)(warp_m0 + (lane & 15)) * RSTRIDE + (uint32_t)((lane >> 4) * 8) * 2;
    const int brow = (lane & 7) + (lane >> 4) * 8;
    const int bk   = ((lane >> 3) & 1) * 8;
    const uint32_t boff = (uint32_t)(warp_n0 + brow) * RSTRIDE + (uint32_t)bk * 2;
    const uint32_t aHi = sb + OFF_AHI + aoff, aLo = sb + OFF_ALO + aoff;
    const uint32_t bHi = sb + OFF_WHI + boff, bLo = sb + OFF_WLO + boff;

    float acc[2][NT8][4];
    // ---- stage 1: z = relu(A W1^T + b1) -> smem A region ----
    run_mainloop<NT8>(aHi, aLo, bHi, bLo, acc);
    __syncthreads();

    const int colq = (lane & 3) * 2;
    #pragma unroll
    for (int mt = 0; mt < 2; mt++) {
        int rr = warp_m0 + mt * 16 + (lane >> 2);
        #pragma unroll
        for (int nt = 0; nt < NT8; nt++) {
            int col = warp_n0 + nt * 8 + colq;
            float2 bb = *(const float2*)(b1 + col);
            float z0 = fmaxf(acc[mt][nt][0] + bb.x, 0.f);
            float z1 = fmaxf(acc[mt][nt][1] + bb.y, 0.f);
            float z2 = fmaxf(acc[mt][nt][2] + bb.x, 0.f);
            float z3 = fmaxf(acc[mt][nt][3] + bb.y, 0.f);
            __nv_bfloat162 h0 = __floats2bfloat162_rn(z0, z1);
            float2 f0 = __bfloat1622float2(h0);
            __nv_bfloat162 l0 = __floats2bfloat162_rn(z0 - f0.x, z1 - f0.y);
            __nv_bfloat162 h1 = __floats2bfloat162_rn(z2, z3);
            float2 f1 = __bfloat1622float2(h1);
            __nv_bfloat162 l1 = __floats2bfloat162_rn(z2 - f1.x, z3 - f1.y);
            *(uint32_t*)(smem + OFF_AHI + toff(rr, col))     = *(uint32_t*)&h0;
            *(uint32_t*)(smem + OFF_ALO + toff(rr, col))     = *(uint32_t*)&l0;
            *(uint32_t*)(smem + OFF_AHI + toff(rr + 8, col)) = *(uint32_t*)&h1;
            *(uint32_t*)(smem + OFF_ALO + toff(rr + 8, col)) = *(uint32_t*)&l1;
        }
    }
    for (int i = tid; i < 128 * 16; i += 256) {
        int r = i >> 4, kc = i & 15;
        *(uint4*)(smem + OFF_WHI + toff(r, kc * 8)) = *(const uint4*)(W2hi + r * 128 + kc * 8);
        *(uint4*)(smem + OFF_WLO + toff(r, kc * 8)) = *(const uint4*)(W2lo + r * 128 + kc * 8);
    }
    __syncthreads();

    // ---- stage 2: h = relu(z W2^T + b2) ----
    run_mainloop<NT8>(aHi, aLo, bHi, bLo, acc);

    if (!HEAD) {
        #pragma unroll
        for (int mt = 0; mt < 2; mt++) {
            int r0 = row0 + warp_m0 + mt * 16 + (lane >> 2);
            #pragma unroll
            for (int nt = 0; nt < NT8; nt++) {
                int col = warp_n0 + nt * 8 + colq;
                float2 bb = *(const float2*)(b2 + col);
                float2 o0, o1;
                o0.x = fmaxf(acc[mt][nt][0] + bb.x, 0.f);
                o0.y = fmaxf(acc[mt][nt][1] + bb.y, 0.f);
                o1.x = fmaxf(acc[mt][nt][2] + bb.x, 0.f);
                o1.y = fmaxf(acc[mt][nt][3] + bb.y, 0.f);
                if (r0 < M)     *(float2*)(C + (size_t)r0 * 128 + col)       = o0;
                if (r0 + 8 < M) *(float2*)(C + (size_t)(r0 + 8) * 128 + col) = o1;
            }
        }
        return;
    }

    // ---- stage 3 (HEAD): h3 -> smem, stage Wout, mainloop NT8=2, log_softmax ----
    __syncthreads();
    #pragma unroll
    for (int mt = 0; mt < 2; mt++) {
        int rr = warp_m0 + mt * 16 + (lane >> 2);
        #pragma unroll
        for (int nt = 0; nt < NT8; nt++) {
            int col = warp_n0 + nt * 8 + colq;
            float2 bb = *(const float2*)(b2 + col);
            float z0 = fmaxf(acc[mt][nt][0] + bb.x, 0.f);
            float z1 = fmaxf(acc[mt][nt][1] + bb.y, 0.f);
            float z2 = fmaxf(acc[mt][nt][2] + bb.x, 0.f);
            float z3 = fmaxf(acc[mt][nt][3] + bb.y, 0.f);
            __nv_bfloat162 h0 = __floats2bfloat162_rn(z0, z1);
            float2 f0 = __bfloat1622float2(h0);
            __nv_bfloat162 l0 = __floats2bfloat162_rn(z0 - f0.x, z1 - f0.y);
            __nv_bfloat162 h1 = __floats2bfloat162_rn(z2, z3);
            float2 f1 = __bfloat1622float2(h1);
            __nv_bfloat162 l1 = __floats2bfloat162_rn(z2 - f1.x, z3 - f1.y);
            *(uint32_t*)(smem + OFF_AHI + toff(rr, col))     = *(uint32_t*)&h0;
            *(uint32_t*)(smem + OFF_ALO + toff(rr, col))     = *(uint32_t*)&l0;
            *(uint32_t*)(smem + OFF_AHI + toff(rr + 8, col)) = *(uint32_t*)&h1;
            *(uint32_t*)(smem + OFF_ALO + toff(rr + 8, col)) = *(uint32_t*)&l1;
        }
    }
    for (int i = tid; i < 64 * 16; i += 256) {
        int r = i >> 4, kc = i & 15;
        *(uint4*)(smem + OFF_WHI + toff(r, kc * 8)) = *(const uint4*)(Whhi + r * 128 + kc * 8);
        *(uint4*)(smem + OFF_WLO + toff(r, kc * 8)) = *(const uint4*)(Whlo + r * 128 + kc * 8);
    }
    __syncthreads();

    const int warp_n0h = (wid >> 1) * 16;     // BN=64, WN=16
    const uint32_t boffh = (uint32_t)(warp_n0h + brow) * RSTRIDE + (uint32_t)bk * 2;
    float acch[2][2][4];
    run_mainloop<2>(aHi, aLo, sb + OFF_WHI + boffh, sb + OFF_WLO + boffh, acch);

    __syncthreads();
    float* Cs = (float*)smem;  // [64][68]
    #pragma unroll
    for (int mt = 0; mt < 2; mt++) {
        int rr = warp_m0 + mt * 16 + (lane >> 2);
        #pragma unroll
        for (int nt = 0; nt < 2; nt++) {
            int col = warp_n0h + nt * 8 + colq;
            float2 bb = *(const float2*)(bh + col);
            Cs[rr * 68 + col]            = acch[mt][nt][0] + bb.x;
            Cs[rr * 68 + col + 1]        = acch[mt][nt][1] + bb.y;
            Cs[(rr + 8) * 68 + col]      = acch[mt][nt][2] + bb.x;
            Cs[(rr + 8) * 68 + col + 1]  = acch[mt][nt][3] + bb.y;
        }
    }
    __syncthreads();
    #pragma unroll
    for (int it = 0; it < 8; it++) {
        int r = wid + it * 8;
        float2 v = *(float2*)&Cs[r * 68 + lane * 2];
        float m = fmaxf(v.x, v.y);
        #pragma unroll
        for (int o = 16; o; o >>= 1) m = fmaxf(m, __shfl_xor_sync(0xffffffffu, m, o));
        float s = expf(v.x - m) + expf(v.y - m);
        #pragma unroll
        for (int o = 16; o; o >>= 1) s += __shfl_xor_sync(0xffffffffu, s, o);
        float ls = logf(s) + m;
        int gr = row0 + r;
        if (gr < M)
            *(float2*)(C + (size_t)gr * 64 + lane * 2) = make_float2(v.x - ls, v.y - ls);
    }
}

// -------------------- CSR build (PDL-chained) --------------------
__global__ void zero_deg_kernel(int n) {
    pdl_launch();
    int i = blockIdx.x * blockDim.x + threadIdx.x;
    if (i < n) { g_indeg[i] = 0; g_outdeg[i] = 0; }
}
__global__ void hist_kernel(const int* __restrict__ row, const int* __restrict__ col, int E) {
    int e = blockIdx.x * blockDim.x + threadIdx.x;
    int r = 0, c = 0;
    if (e < E) { r = row[e]; c = col[e]; }
    pdl_wait();
    pdl_launch();
    if (e < E) {
        atomicAdd(&g_indeg[c], 1);
        atomicAdd(&g_outdeg[r], 1);
    }
}
__global__ __launch_bounds__(1024) void scan_block_kernel(int* __restrict__ out, int n) {
    __shared__ int wsum[32];
    pdl_wait();
    pdl_launch();
    int i = blockIdx.x * 1024 + threadIdx.x;
    int lane = threadIdx.x & 31, wid = threadIdx.x >> 5;
    int orig = (i < n) ? g_indeg[i] : 0;
    int v = orig;
    #pragma unroll
    for (int o = 1; o < 32; o <<= 1) {
        int t = __shfl_up_sync(0xffffffffu, v, o);
        if (lane >= o) v += t;
    }
    if (lane == 31) wsum[wid] = v;
    __syncthreads();
    if (wid == 0) {
        int s = wsum[lane];
        #pragma unroll
        for (int o = 1; o < 32; o <<= 1) {
            int t = __shfl_up_sync(0xffffffffu, s, o);
            if (lane >= o) s += t;
        }
        wsum[lane] = s;
    }
    __syncthreads();
    int excl = v - orig + (wid > 0 ? wsum[wid - 1] : 0);
    if (i < n) out[i] = excl;
    if (threadIdx.x == 1023) g_blocksum[blockIdx.x] = excl + orig;
}
__global__ void scan_top_kernel(int nb) {
    __shared__ int ws[2];
    pdl_wait();
    pdl_launch();
    int t = threadIdx.x, lane = t & 31, w = t >> 5;
    int v = (t < nb) ? g_blocksum[t] : 0;
    int s = v;
    #pragma unroll
    for (int o = 1; o < 32; o <<= 1) {
        int x = __shfl_up_sync(0xffffffffu, s, o);
        if (lane >= o) s += x;
    }
    if (lane == 31) ws[w] = s;
    __syncthreads();
    int excl = s - v + (w == 1 ? ws[0] : 0);
    if (t < nb) g_blocksum[t] = excl;
}
__global__ void finalize_kernel(const int* __restrict__ partial, int n) {
    pdl_wait();
    pdl_launch();
    int i = blockIdx.x * blockDim.x + threadIdx.x;
    if (i >= n) return;
    int s = partial[i] + g_blocksum[i >> 10];
    g_start[i] = s;
    g_ptr[i]   = s;
    g_coef[i]  = 1.0f / (float)(g_outdeg[i] + 1);
}
__global__ void scatter_kernel(const int* __restrict__ row, const int* __restrict__ col, int E) {
    int e = blockIdx.x * blockDim.x + threadIdx.x;
    int r = 0, c = 0;
    if (e < E) { r = row[e]; c = col[e]; }
    pdl_wait();
    pdl_launch();
    if (e < E) {
        int p = atomicAdd(&g_ptr[c], 1);
        g_eid[p] = r;
    }
}

// -------------------- gather aggregation (fp32, 2-deep pipelined, PDL) ------------------
template<bool ATT>
__global__ void agg_kernel(const float* __restrict__ src, float* __restrict__ dst, int n) {
    int node = (blockIdx.x * blockDim.x + threadIdx.x) >> 5;
    int lane = threadIdx.x & 31;
    if (node >= n) { pdl_wait(); pdl_launch(); return; }
    int s = g_start[node], e = s + g_indeg[node];
    float cself = ATT ? g_coef[node] : 1.0f;
    int myeid = (s + lane < e) ? __ldg(&g_eid[s + lane]) : 0;
    pdl_wait();
    pdl_launch();
    float4 acc = *(const float4*)(src + (size_t)node * 128 + lane * 4);
    if (ATT) { acc.x *= cself; acc.y *= cself; acc.z *= cself; acc.w *= cself; }
    float4 acc2 = make_float4(0.f, 0.f, 0.f, 0.f);
    for (int j0 = s; j0 < e; j0 += 32) {
        int nb = min(32, e - j0);
        int cur = myeid;
        int jn = j0 + 32;
        if (jn < e) myeid = (jn + lane < e) ? __ldg(&g_eid[jn + lane]) : 0;
        int t = 0;
        for (; t + 1 < nb; t += 2) {
            int r0 = __shfl_sync(0xffffffffu, cur, t);
            int r1 = __shfl_sync(0xffffffffu, cur, t + 1);
            float4 v0 = *(const float4*)(src + (size_t)r0 * 128 + lane * 4);
            float4 v1 = *(const float4*)(src + (size_t)r1 * 128 + lane * 4);
            float c0 = ATT ? g_coef[r0] : 1.0f;
            float c1 = ATT ? g_coef[r1] : 1.0f;
            acc.x  = fmaf(c0, v0.x, acc.x);  acc.y  = fmaf(c0, v0.y, acc.y);
            acc.z  = fmaf(c0, v0.z, acc.z);  acc.w  = fmaf(c0, v0.w, acc.w);
            acc2.x = fmaf(c1, v1.x, acc2.x); acc2.y = fmaf(c1, v1.y, acc2.y);
            acc2.z = fmaf(c1, v1.z, acc2.z); acc2.w = fmaf(c1, v1.w, acc2.w);
        }
        if (t < nb) {
            int r0 = __shfl_sync(0xffffffffu, cur, t);
            float4 v0 = *(const float4*)(src + (size_t)r0 * 128 + lane * 4);
            float c0 = ATT ? g_coef[r0] : 1.0f;
            acc.x = fmaf(c0, v0.x, acc.x); acc.y = fmaf(c0, v0.y, acc.y);
            acc.z = fmaf(c0, v0.z, acc.z); acc.w = fmaf(c0, v0.w, acc.w);
        }
    }
    acc.x += acc2.x; acc.y += acc2.y; acc.z += acc2.z; acc.w += acc2.w;
    if (ATT) {
        acc.x = fmaxf(acc.x, 0.f); acc.y = fmaxf(acc.y, 0.f);
        acc.z = fmaxf(acc.z, 0.f); acc.w = fmaxf(acc.w, 0.f);
    }
    *(float4*)(dst + (size_t)node * 128 + lane * 4) = acc;
}

// -------------------- launch --------------------
extern "C" void kernel_launch(void* const* d_in, const int* in_sizes, int n_in,
                              void* d_out, int out_size)
{
    const float* x     = (const float*)d_in[0];
    const int*   ei    = (const int*)  d_in[1];
    const float* fl_W  = (const float*)d_in[2];
    const float* fl_b  = (const float*)d_in[3];
    // d_in[4] = fl_att : softmax over identical per-segment logits is uniform -> unused
    const float* g1_W1 = (const float*)d_in[5];
    const float* g1_b1 = (const float*)d_in[6];
    const float* g1_W2 = (const float*)d_in[7];
    const float* g1_b2 = (const float*)d_in[8];
    const float* g2_W1 = (const float*)d_in[9];
    const float* g2_b1 = (const float*)d_in[10];
    const float* g2_W2 = (const float*)d_in[11];
    const float* g2_b2 = (const float*)d_in[12];
    const float* out_W = (const float*)d_in[13];
    const float* out_b = (const float*)d_in[14];
    float* out = (float*)d_out;

    const int N = in_sizes[0] / HDIM;
    const int E = in_sizes[1] / 2;
    const int* row = ei;
    const int* col = ei + E;

    float *pH = nullptr, *pB = nullptr, *pC = nullptr;
    int* pPtr = nullptr;
    __nv_bfloat16 *pWhi = nullptr, *pWlo = nullptr;
    cudaGetSymbolAddress((void**)&pH, g_h);
    cudaGetSymbolAddress((void**)&pB, g_B);
    cudaGetSymbolAddress((void**)&pC, g_C);
    cudaGetSymbolAddress((void**)&pPtr, g_ptr);
    cudaGetSymbolAddress((void**)&pWhi, g_Whi);
    cudaGetSymbolAddress((void**)&pWlo, g_Wlo);

    const int smem128 = 2 * 128 * RSTRIDE + 2 * 64 * RSTRIDE;  // 104448
    cudaFuncSetAttribute(gemm_mma<128, false, 1>, cudaFuncAttributeMaxDynamicSharedMemorySize, smem128);
    cudaFuncSetAttribute(gin_mlp<false>,          cudaFuncAttributeMaxDynamicSharedMemorySize, smem128);
    cudaFuncSetAttribute(gin_mlp<true>,           cudaFuncAttributeMaxDynamicSharedMemorySize, smem128);

    static cudaStream_t s_side = [] {
        cudaStream_t s; cudaStreamCreateWithFlags(&s, cudaStreamNonBlocking); return s;
    }();
    static cudaEvent_t s_fork = [] {
        cudaEvent_t e; cudaEventCreateWithFlags(&e, cudaEventDisableTiming); return e;
    }();
    static cudaEvent_t s_join = [] {
        cudaEvent_t e; cudaEventCreateWithFlags(&e, cudaEventDisableTiming); return e;
    }();

    const int T = 256;
    const int gemmGrid  = (N + 63) / 64;
    const int edgeThG   = (E + T - 1) / T;
    const int nodeThG   = (N + T - 1) / T;
    const int nodeWarpG = (N * 32 + T - 1) / T;
    const int scanBlocks = (N + 1023) / 1024;

    cudaLaunchAttribute pdlAttr[1];
    pdlAttr[0].id = cudaLaunchAttributeProgrammaticStreamSerialization;
    pdlAttr[0].val.programmaticStreamSerializationAllowed = 1;
    auto mkCfg = [&](int grid, int blk, int smem, cudaStream_t st) {
        cudaLaunchConfig_t c = {};
        c.gridDim = dim3(grid); c.blockDim = dim3(blk);
        c.dynamicSmemBytes = (size_t)smem; c.stream = st;
        c.attrs = pdlAttr; c.numAttrs = 1;
        return c;
    };

    // ---- fork: CSR build on side stream (PDL-chained) ----
    cudaEventRecord(s_fork, 0);
    cudaStreamWaitEvent(s_side, s_fork, 0);

    { cudaLaunchConfig_t c = mkCfg(nodeThG, T, 0, s_side);
      cudaLaunchKernelEx(&c, zero_deg_kernel, N); }
    { cudaLaunchConfig_t c = mkCfg(edgeThG, T, 0, s_side);
      cudaLaunchKernelEx(&c, hist_kernel, row, col, E); }
    { cudaLaunchConfig_t c = mkCfg(scanBlocks, 1024, 0, s_side);
      cudaLaunchKernelEx(&c, scan_block_kernel, pPtr, N); }
    { cudaLaunchConfig_t c = mkCfg(1, 64, 0, s_side);
      cudaLaunchKernelEx(&c, scan_top_kernel, scanBlocks); }
    { cudaLaunchConfig_t c = mkCfg(nodeThG, T, 0, s_side);
      cudaLaunchKernelEx(&c, finalize_kernel, (const int*)pPtr, N); }
    { cudaLaunchConfig_t c = mkCfg(edgeThG, T, 0, s_side);
      cudaLaunchKernelEx(&c, scatter_kernel, row, col, E); }
    cudaEventRecord(s_join, s_side);

    wsplit_kernel<<<(6 * 16384 + T - 1) / T, T>>>(fl_W, g1_W1, g1_W2, g2_W1, g2_W2, out_W);
    {   // gemm1: stage A(x) during wsplit tail (PRO=1)
        cudaLaunchConfig_t c = mkCfg(gemmGrid, T, smem128, 0);
        cudaLaunchKernelEx(&c, gemm_mma<128, false, 1>, x, (const __nv_bfloat16*)pWhi,
                           (const __nv_bfloat16*)pWlo, fl_b, pH, N);
    }

    cudaStreamWaitEvent(0, s_join, 0);

    // ---- network: 6 main-chain kernels, PDL-chained ----
    { cudaLaunchConfig_t c = mkCfg(nodeWarpG, T, 0, 0);
      cudaLaunchKernelEx(&c, agg_kernel<true>,  (const float*)pH, pB, N); }       // h1
    { cudaLaunchConfig_t c = mkCfg(nodeWarpG, T, 0, 0);
      cudaLaunchKernelEx(&c, agg_kernel<false>, (const float*)pB, pC, N); }       // z1
    { cudaLaunchConfig_t c = mkCfg(gemmGrid, T, smem128, 0);                      // h2 = GIN1 MLP
      cudaLaunchKernelEx(&c, gin_mlp<false>, (const float*)pC,
                         (const __nv_bfloat16*)(pWhi + 16384), (const __nv_bfloat16*)(pWlo + 16384), g1_b1,
                         (const __nv_bfloat16*)(pWhi + 2 * 16384), (const __nv_bfloat16*)(pWlo + 2 * 16384), g1_b2,
                         (const __nv_bfloat16*)nullptr, (const __nv_bfloat16*)nullptr, (const float*)nullptr,
                         pH, N); }
    { cudaLaunchConfig_t c = mkCfg(nodeWarpG, T, 0, 0);
      cudaLaunchKernelEx(&c, agg_kernel<false>, (const float*)pH, pB, N); }       // z2
    { cudaLaunchConfig_t c = mkCfg(gemmGrid, T, smem128, 0);                      // GIN2 MLP + head + lsm
      cudaLaunchKernelEx(&c, gin_mlp<true>, (const float*)pB,
                         (const __nv_bfloat16*)(pWhi + 3 * 16384), (const __nv_bfloat16*)(pWlo + 3 * 16384), g2_b1,
                         (const __nv_bfloat16*)(pWhi + 4 * 16384), (const __nv_bfloat16*)(pWlo + 4 * 16384), g2_b2,
                         (const __nv_bfloat16*)(pWhi + 5 * 16384), (const __nv_bfloat16*)(pWlo + 5 * 16384), out_b,
                         out, N); }
}